// round 13
// baseline (speedup 1.0000x reference)
#include <cuda_runtime.h>
#include <cstdint>

#define N_NODES 50000
#define N_EDGES 800000
#define D       128
#define RT      8                      // rows per warp tile (gemm1)
#define RTF     4                      // rows per warp tile (final)

#define SCAN_ITEMS 4
#define SCAN_BLK   256
#define SCAN_CHUNK (SCAN_BLK * SCAN_ITEMS)                       // 1024
#define SCAN_NBLK  ((N_NODES + SCAN_CHUNK - 1) / SCAN_CHUNK)     // 49

#define DEG_BLOCKS  96
#define GEMM_BLOCKS 296

// ---- packed f32x2 helpers (FFMA2: 2 fp32 FMAs per issue slot, rt~1/SMSP) ----
#define FMA_X2(acc, a, b) \
    asm("fma.rn.f32x2 %0, %1, %2, %0;" : "+l"(acc) : "l"(a), "l"(b))
#define MUL_X2(out, a, b) \
    asm("mul.rn.f32x2 %0, %1, %2;" : "=l"(out) : "l"(a), "l"(b))
#define PACK_DUP(out, xi) \
    asm("mov.b64 %0, {%1, %1};" : "=l"(out) : "r"(xi))

__device__ __forceinline__ float f4c(const float4& v, int kk) {
    return kk == 0 ? v.x : kk == 1 ? v.y : kk == 2 ? v.z : v.w;
}

// ---- scratch (device globals; no allocation allowed) ----
__device__ __align__(16) float g_z[(size_t)N_NODES * D];    // y = x @ Wc (UNSCALED)
__device__ __align__(16) float g_dinv[N_NODES];
__device__ __align__(16) int   g_deg[N_NODES + 4];          // zero-init; re-zeroed by k_scan
__device__ int   g_off[N_NODES + 1];
__device__ int   g_cursor[N_NODES];
__device__ int   g_csr_src[N_EDGES];
__device__ int   g_bsum[SCAN_NBLK];
__device__ int   g_scan_arrive;                             // 0-init; reset by k_fill

// ---------------------------------------------------------------------------
__device__ __forceinline__ int detect_is64_block(const void* ei, int* s_flag) {
    if (threadIdx.x == 0) {
        const long long* p = (const long long*)ei;
        int use64 = 1;
        for (int i = 0; i < 64; i++)
            if ((unsigned long long)p[i] >> 32) { use64 = 0; break; }
        *s_flag = use64;
    }
    __syncthreads();
    return *s_flag;
}

__device__ __forceinline__ int edge_at(const void* ei, int use64, size_t idx) {
    return use64 ? (int)((const long long*)ei)[idx]
                 : ((const int*)ei)[idx];
}

// ---------------------------------------------------------------------------
// K1 (fused): blocks [0,DEG_BLOCKS) in-degree histogram; rest compute
// y = x @ Wc (UNSCALED -> independent of degree/scan) with smem staging.
// ---------------------------------------------------------------------------
__global__ __launch_bounds__(256) void k_pre(const float* __restrict__ x,
                                             const float* __restrict__ Wc,
                                             const void* __restrict__ ei) {
    extern __shared__ float sm[];

    if (blockIdx.x < DEG_BLOCKS) {
        __shared__ int s_flag;
        int use64 = detect_is64_block(ei, &s_flag);
        int tid = blockIdx.x * blockDim.x + threadIdx.x;
        int stride = DEG_BLOCKS * blockDim.x;
        for (int e = tid; e < N_EDGES; e += stride) {
            unsigned d = (unsigned)edge_at(ei, use64, (size_t)N_EDGES + e);
            if (d < N_NODES) atomicAdd(&g_deg[d], 1);
        }
        return;
    }

    float* Ws = sm;                          // 16384 floats
    float* xt = sm + D * D;                  // 8 warps * 8 rows * 128
    int tid = threadIdx.x, warp = tid >> 5, lane = tid & 31;
    int bid = blockIdx.x - DEG_BLOCKS;

    for (int i = tid; i < D * D / 4; i += 256)
        ((float4*)Ws)[i] = ((const float4*)Wc)[i];
    __syncthreads();

    float* xw = xt + warp * (RT * D);
    const int ngroups = (N_NODES + RT - 1) / RT;
    const int wstride = GEMM_BLOCKS * 8;
    for (int g = bid * 8 + warp; g < ngroups; g += wstride) {
        int row0 = g * RT;
#pragma unroll
        for (int r = 0; r < RT; r++) {
            int row = row0 + r;
            float4 v = (row < N_NODES) ? ((const float4*)(x + (size_t)row * D))[lane]
                                       : make_float4(0.f, 0.f, 0.f, 0.f);
            ((float4*)(xw + r * D))[lane] = v;
        }
        __syncwarp();

        unsigned long long a0[RT], a1[RT];
#pragma unroll
        for (int r = 0; r < RT; r++) { a0[r] = 0ull; a1[r] = 0ull; }
#pragma unroll 4
        for (int k = 0; k < D; k++) {
            ulonglong2 w = ((const ulonglong2*)(Ws + k * D))[lane];
#pragma unroll
            for (int r = 0; r < RT; r++) {
                unsigned xi = __float_as_uint(xw[r * D + k]);
                unsigned long long xp;
                PACK_DUP(xp, xi);
                FMA_X2(a0[r], xp, w.x);
                FMA_X2(a1[r], xp, w.y);
            }
        }
#pragma unroll
        for (int r = 0; r < RT; r++) {
            int row = row0 + r;
            if (row < N_NODES)
                ((ulonglong2*)(g_z + (size_t)row * D))[lane] = make_ulonglong2(a0[r], a1[r]);
        }
        __syncwarp();
    }
}

// ---------------------------------------------------------------------------
// K2: merged scan — block sum, publish, spin to full arrival, then local scan
// -> off, cursor, dinv. Re-zeroes g_deg for the next replay.
// ---------------------------------------------------------------------------
__global__ __launch_bounds__(SCAN_BLK) void k_scan() {
    __shared__ int sh[SCAN_BLK];
    __shared__ int warpsum[SCAN_BLK / 32];
    __shared__ int s_base;
    int t = threadIdx.x, b = blockIdx.x;

    int idx = b * SCAN_CHUNK + t * SCAN_ITEMS;
    int4 v = (idx < N_NODES + 4) ? ((const int4*)g_deg)[idx >> 2]
                                 : make_int4(0, 0, 0, 0);
    if (idx < N_NODES + 4)
        ((int4*)g_deg)[idx >> 2] = make_int4(0, 0, 0, 0);   // reset for replay
    int d0 = (idx + 0 < N_NODES) ? v.x : 0;
    int d1 = (idx + 1 < N_NODES) ? v.y : 0;
    int d2 = (idx + 2 < N_NODES) ? v.z : 0;
    int d3 = (idx + 3 < N_NODES) ? v.w : 0;
    int s = d0 + d1 + d2 + d3;
    sh[t] = s;

    int ws = s;
#pragma unroll
    for (int o = 16; o > 0; o >>= 1) ws += __shfl_down_sync(0xffffffffu, ws, o);
    if ((t & 31) == 0) warpsum[t >> 5] = ws;
    __syncthreads();

    if (t == 0) {
        int tot = 0;
#pragma unroll
        for (int i = 0; i < SCAN_BLK / 32; i++) tot += warpsum[i];
        g_bsum[b] = tot;
        __threadfence();
        atomicAdd(&g_scan_arrive, 1);
        while (atomicAdd(&g_scan_arrive, 0) < SCAN_NBLK) {}
    }
    __syncthreads();

    if (t < 32) {
        int vs = 0;
        for (int i = t; i < b; i += 32) vs += atomicAdd(&g_bsum[i], 0);
#pragma unroll
        for (int o = 16; o > 0; o >>= 1) vs += __shfl_down_sync(0xffffffffu, vs, o);
        if (t == 0) s_base = vs;
    }
    __syncthreads();

#pragma unroll
    for (int d = 1; d < SCAN_BLK; d <<= 1) {
        int u = (t >= d) ? sh[t - d] : 0;
        __syncthreads();
        sh[t] += u;
        __syncthreads();
    }
    int run = s_base + ((t > 0) ? sh[t - 1] : 0);
    int dg[4] = {d0, d1, d2, d3};
#pragma unroll
    for (int j = 0; j < 4; j++) {
        int i = idx + j;
        if (i < N_NODES) {
            g_off[i] = run;
            g_cursor[i] = run;
            g_dinv[i] = rsqrtf((float)(dg[j] + 1));
            run += dg[j];
        }
    }
    if (b == SCAN_NBLK - 1 && t == SCAN_BLK - 1) g_off[N_NODES] = run;
}

// ---------------------------------------------------------------------------
// K3: fill CSR at full grid; also resets the scan arrival counter.
// ---------------------------------------------------------------------------
__global__ void k_fill(const void* __restrict__ ei) {
    if (blockIdx.x == 0 && threadIdx.x == 0) g_scan_arrive = 0;
    __shared__ int s_flag;
    int use64 = detect_is64_block(ei, &s_flag);
    int tid = blockIdx.x * blockDim.x + threadIdx.x;
    int stride = gridDim.x * blockDim.x;
    for (int e = tid; e < N_EDGES; e += stride) {
        unsigned s = (unsigned)edge_at(ei, use64, e);
        unsigned d = (unsigned)edge_at(ei, use64, (size_t)N_EDGES + e);
        if (d < N_NODES && s < N_NODES) {
            int pos = atomicAdd(&g_cursor[d], 1);
            g_csr_src[pos] = (int)s;
        }
    }
}

// ---------------------------------------------------------------------------
// K4: 1024-thread blocks, RTF=4 rows per warp tile. Gather of UNSCALED y with
// per-source dinv folded as FFMA2 (issue-neutral); idx+dinv prefetched one
// row ahead into smem. Epilogue: out = h @ (I+Wt) + x @ (W0-Wt).
// ---------------------------------------------------------------------------
__global__ __launch_bounds__(1024, 1) void k_final(const float* __restrict__ x,
                                                   const float* __restrict__ bc,
                                                   const float* __restrict__ W0,
                                                   const float* __restrict__ Wt,
                                                   float* __restrict__ out) {
    extern __shared__ float sm[];
    float* M1s = sm;                          // 16384
    float* M2s = sm + D * D;                  // 16384
    float* bcs = sm + 2 * D * D;              // 128
    float* ht  = bcs + D;                     // 32 warps * RTF * 128 = 16384
    int*   ibase = (int*)(ht + 32 * RTF * D); // 32 warps * 64 ints
    float* dbase = (float*)(ibase + 32 * 64); // 32 warps * 64 floats
    int tid = threadIdx.x, warp = tid >> 5, lane = tid & 31;

    for (int i = tid; i < D * D / 4; i += 1024) {
        float4 wt = ((const float4*)Wt)[i];
        float4 w0 = ((const float4*)W0)[i];
        int r = (i * 4) / D, c0 = (i * 4) % D;
        float m1v[4] = {wt.x, wt.y, wt.z, wt.w};
        int dd = r - c0;
        if (dd >= 0 && dd < 4) m1v[dd] += 1.0f;
        ((float4*)M1s)[i] = make_float4(m1v[0], m1v[1], m1v[2], m1v[3]);
        ((float4*)M2s)[i] = make_float4(w0.x - wt.x, w0.y - wt.y,
                                        w0.z - wt.z, w0.w - wt.w);
    }
    if (tid < D) bcs[tid] = bc[tid];
    __syncthreads();

    float* htw  = ht + warp * (RTF * D);
    int*   ibuf = ibase + warp * 64;          // two 32-entry halves
    float* dbuf = dbase + warp * 64;

    const int ngroups = (N_NODES + RTF - 1) / RTF;
    const int wstride = gridDim.x * 32;
    for (int g = blockIdx.x * 32 + warp; g < ngroups; g += wstride) {
        int row0 = g * RTF;

        int off_l = 0;
        if (lane <= RTF) {
            int rr = row0 + lane;
            off_l = __ldg(&g_off[rr < N_NODES ? rr : N_NODES]);
        }
        int rowE[RTF + 1];
#pragma unroll
        for (int r = 0; r <= RTF; r++)
            rowE[r] = __shfl_sync(0xffffffffu, off_l, r);

        {
            int n0 = rowE[1] - rowE[0];
            if (lane < (n0 < 32 ? n0 : 32)) {
                int ii = __ldg(&g_csr_src[rowE[0] + lane]);
                ibuf[lane] = ii;
                dbuf[lane] = __ldg(&g_dinv[ii]);
            }
        }

        // ---- gather phase with one-row-ahead idx+dinv prefetch
#pragma unroll
        for (int r = 0; r < RTF; r++) {
            __syncwarp();
            int*   cur  = ibuf + ((r & 1) << 5);
            float* curd = dbuf + ((r & 1) << 5);
            if (r + 1 < RTF) {
                int*   nxt  = ibuf + (((r + 1) & 1) << 5);
                float* nxtd = dbuf + (((r + 1) & 1) << 5);
                int nn = rowE[r + 2] - rowE[r + 1];
                if (lane < (nn < 32 ? nn : 32)) {
                    int ii = __ldg(&g_csr_src[rowE[r + 1] + lane]);
                    nxt[lane] = ii;
                    nxtd[lane] = __ldg(&g_dinv[ii]);
                }
            }

            int row = row0 + r;
            if (row >= N_NODES) {
                ((float4*)(htw + r * D))[lane] = make_float4(0.f, 0.f, 0.f, 0.f);
                continue;
            }
            size_t base = (size_t)row * D;
            float sr = __ldg(&g_dinv[row]);
            unsigned long long srp;
            PACK_DUP(srp, __float_as_uint(sr));

            // self loop: acc = dinv_row * y_row
            ulonglong2 yr = ((const ulonglong2*)(g_z + base))[lane];
            unsigned long long a0 = 0ull, a1 = 0ull;
            FMA_X2(a0, srp, yr.x);
            FMA_X2(a1, srp, yr.y);

            int n = rowE[r + 1] - rowE[r];
            int m = n < 32 ? n : 32;
            int i = 0;
            for (; i + 3 < m; i += 4) {
                int s0 = cur[i];     int s1 = cur[i + 1];
                int s2 = cur[i + 2]; int s3 = cur[i + 3];
                float e0 = curd[i];     float e1 = curd[i + 1];
                float e2 = curd[i + 2]; float e3 = curd[i + 3];
                ulonglong2 v0 = ((const ulonglong2*)(g_z + (size_t)s0 * D))[lane];
                ulonglong2 v1 = ((const ulonglong2*)(g_z + (size_t)s1 * D))[lane];
                ulonglong2 v2 = ((const ulonglong2*)(g_z + (size_t)s2 * D))[lane];
                ulonglong2 v3 = ((const ulonglong2*)(g_z + (size_t)s3 * D))[lane];
                unsigned long long p0, p1, p2, p3;
                PACK_DUP(p0, __float_as_uint(e0));
                PACK_DUP(p1, __float_as_uint(e1));
                PACK_DUP(p2, __float_as_uint(e2));
                PACK_DUP(p3, __float_as_uint(e3));
                FMA_X2(a0, p0, v0.x); FMA_X2(a1, p0, v0.y);
                FMA_X2(a0, p1, v1.x); FMA_X2(a1, p1, v1.y);
                FMA_X2(a0, p2, v2.x); FMA_X2(a1, p2, v2.y);
                FMA_X2(a0, p3, v3.x); FMA_X2(a1, p3, v3.y);
            }
            for (; i < m; i++) {
                int s0 = cur[i];
                float e0 = curd[i];
                ulonglong2 v0 = ((const ulonglong2*)(g_z + (size_t)s0 * D))[lane];
                unsigned long long p0;
                PACK_DUP(p0, __float_as_uint(e0));
                FMA_X2(a0, p0, v0.x); FMA_X2(a1, p0, v0.y);
            }
            // rare tail: degree > 32
            for (int e = rowE[r] + 32; e < rowE[r + 1]; e++) {
                int s0 = __ldg(&g_csr_src[e]);
                float e0 = __ldg(&g_dinv[s0]);
                ulonglong2 v0 = ((const ulonglong2*)(g_z + (size_t)s0 * D))[lane];
                unsigned long long p0;
                PACK_DUP(p0, __float_as_uint(e0));
                FMA_X2(a0, p0, v0.x); FMA_X2(a1, p0, v0.y);
            }

            // h = dinv_row * acc + bc
            ulonglong2 bcp = ((const ulonglong2*)bcs)[lane];
            unsigned long long h0 = bcp.x, h1 = bcp.y;
            FMA_X2(h0, srp, a0);
            FMA_X2(h1, srp, a1);
            ((ulonglong2*)(htw + r * D))[lane] = make_ulonglong2(h0, h1);
        }
        __syncwarp();

        // ---- dual GEMM: o[r] = h[r] @ M1 + x[r] @ M2  (packed f32x2)
        unsigned long long o0[RTF], o1[RTF];
#pragma unroll
        for (int r = 0; r < RTF; r++) { o0[r] = 0ull; o1[r] = 0ull; }
#pragma unroll 2
        for (int j = 0; j < D / 4; j++) {
            float4 xv[RTF];
#pragma unroll
            for (int r = 0; r < RTF; r++) {
                int row = row0 + r;
                xv[r] = (row < N_NODES)
                      ? __ldg(&((const float4*)(x + (size_t)row * D))[j])
                      : make_float4(0.f, 0.f, 0.f, 0.f);
            }
#pragma unroll
            for (int kk = 0; kk < 4; kk++) {
                int k = 4 * j + kk;
                ulonglong2 m1 = ((const ulonglong2*)(M1s + k * D))[lane];
                ulonglong2 m2 = ((const ulonglong2*)(M2s + k * D))[lane];
#pragma unroll
                for (int r = 0; r < RTF; r++) {
                    unsigned hi_ = __float_as_uint(htw[r * D + k]);
                    unsigned xi_ = __float_as_uint(f4c(xv[r], kk));
                    unsigned long long hp, xp;
                    PACK_DUP(hp, hi_);
                    PACK_DUP(xp, xi_);
                    FMA_X2(o0[r], hp, m1.x);
                    FMA_X2(o1[r], hp, m1.y);
                    FMA_X2(o0[r], xp, m2.x);
                    FMA_X2(o1[r], xp, m2.y);
                }
            }
        }
#pragma unroll
        for (int r = 0; r < RTF; r++) {
            int row = row0 + r;
            if (row < N_NODES)
                ((ulonglong2*)(out + (size_t)row * D))[lane] = make_ulonglong2(o0[r], o1[r]);
        }
        __syncwarp();
    }
}

// ---------------------------------------------------------------------------
extern "C" void kernel_launch(void* const* d_in, const int* in_sizes, int n_in,
                              void* d_out, int out_size) {
    const float* x  = (const float*)d_in[0];
    const void*  ei = d_in[1];
    const float* Wc = (const float*)d_in[2];
    const float* bc = (const float*)d_in[3];
    const float* W0 = (const float*)d_in[4];
    const float* Wt = (const float*)d_in[5];

    {
        const float* fx = nullptr; const void* fei = nullptr;
        const float* fbc = nullptr;
        const float* w[3] = {nullptr, nullptr, nullptr}; int nw = 0;
        for (int i = 0; i < n_in; i++) {
            int sz = in_sizes[i];
            if (sz == N_NODES * D)                           fx  = (const float*)d_in[i];
            else if (sz == 2 * N_EDGES || sz == 4 * N_EDGES) fei = d_in[i];
            else if (sz == D)                                fbc = (const float*)d_in[i];
            else if (sz == D * D && nw < 3)                  w[nw++] = (const float*)d_in[i];
        }
        if (fx)  x  = fx;
        if (fei) ei = fei;
        if (fbc) bc = fbc;
        if (nw == 3) { Wc = w[0]; W0 = w[1]; Wt = w[2]; }
    }
    float* out = (float*)d_out;

    int smem_pre   = (D * D + 8 * RT * D) * (int)sizeof(float);               // 98,304 B
    int smem_final = (2 * D * D + D + 32 * RTF * D) * (int)sizeof(float)
                     + 32 * 64 * (int)(sizeof(int) + sizeof(float));           // 213,504 B
    cudaFuncSetAttribute(k_pre, cudaFuncAttributeMaxDynamicSharedMemorySize, smem_pre);
    cudaFuncSetAttribute(k_final, cudaFuncAttributeMaxDynamicSharedMemorySize, smem_final);

    k_pre<<<DEG_BLOCKS + GEMM_BLOCKS, 256, smem_pre>>>(x, Wc, ei);
    k_scan<<<SCAN_NBLK, SCAN_BLK>>>();
    k_fill<<<512, 256>>>(ei);
    k_final<<<148, 1024, smem_final>>>(x, bc, W0, Wt, out);
}

// round 14
// speedup vs baseline: 1.1759x; 1.1759x over previous
#include <cuda_runtime.h>
#include <cstdint>

#define N_NODES 50000
#define N_EDGES 800000
#define D       128
#define RT      8                      // rows per warp tile (gemm1)
#define RTF     8                      // rows per warp tile (final)
#define FWARPS  16                     // warps per block in k_final

#define SCAN_ITEMS 4
#define SCAN_BLK   256
#define SCAN_CHUNK (SCAN_BLK * SCAN_ITEMS)                       // 1024
#define SCAN_NBLK  ((N_NODES + SCAN_CHUNK - 1) / SCAN_CHUNK)     // 49

#define FILL_BLOCKS 96
#define GEMM_BLOCKS 296

// ---- packed f32x2 helpers ----
#define FMA_X2(acc, a, b) \
    asm("fma.rn.f32x2 %0, %1, %2, %0;" : "+l"(acc) : "l"(a), "l"(b))
#define MUL_X2(out, a, b) \
    asm("mul.rn.f32x2 %0, %1, %2;" : "=l"(out) : "l"(a), "l"(b))
#define PACK_DUP(out, xi) \
    asm("mov.b64 %0, {%1, %1};" : "=l"(out) : "r"(xi))

__device__ __forceinline__ float f4c(const float4& v, int kk) {
    return kk == 0 ? v.x : kk == 1 ? v.y : kk == 2 ? v.z : v.w;
}

// ---- scratch (device globals; no allocation allowed) ----
__device__ __align__(16) float g_z[(size_t)N_NODES * D];    // z = dinv * (x @ Wc)
__device__ __align__(16) float g_dinv[N_NODES];
__device__ __align__(16) int   g_deg[N_NODES + 4];          // zero-init; re-zeroed by scanC
__device__ int   g_off[N_NODES + 1];
__device__ int   g_cursor[N_NODES];
__device__ int   g_csr_src[N_EDGES];
__device__ int   g_bsum[SCAN_NBLK];

// ---------------------------------------------------------------------------
__device__ __forceinline__ int detect_is64_block(const void* ei, int* s_flag) {
    if (threadIdx.x == 0) {
        const long long* p = (const long long*)ei;
        int use64 = 1;
        for (int i = 0; i < 64; i++)
            if ((unsigned long long)p[i] >> 32) { use64 = 0; break; }
        *s_flag = use64;
    }
    __syncthreads();
    return *s_flag;
}

__device__ __forceinline__ int edge_at(const void* ei, int use64, size_t idx) {
    return use64 ? (int)((const long long*)ei)[idx]
                 : ((const int*)ei)[idx];
}

// ---------------------------------------------------------------------------
__global__ void k_degree(const void* __restrict__ ei) {
    __shared__ int s_flag;
    int use64 = detect_is64_block(ei, &s_flag);
    int tid = blockIdx.x * blockDim.x + threadIdx.x;
    int stride = gridDim.x * blockDim.x;
    for (int e = tid; e < N_EDGES; e += stride) {
        unsigned d = (unsigned)edge_at(ei, use64, (size_t)N_EDGES + e);
        if (d < N_NODES) atomicAdd(&g_deg[d], 1);
    }
}

// ---------------------------------------------------------------------------
__global__ __launch_bounds__(SCAN_BLK) void k_scanA() {
    __shared__ int warpsum[SCAN_BLK / 32];
    int t = threadIdx.x, b = blockIdx.x;
    int idx = b * SCAN_CHUNK + t * SCAN_ITEMS;
    int4 v = (idx < N_NODES + 4) ? ((const int4*)g_deg)[idx >> 2]
                                 : make_int4(0, 0, 0, 0);
    int s = 0;
    if (idx + 0 < N_NODES) s += v.x;
    if (idx + 1 < N_NODES) s += v.y;
    if (idx + 2 < N_NODES) s += v.z;
    if (idx + 3 < N_NODES) s += v.w;
#pragma unroll
    for (int o = 16; o > 0; o >>= 1) s += __shfl_down_sync(0xffffffffu, s, o);
    if ((t & 31) == 0) warpsum[t >> 5] = s;
    __syncthreads();
    if (t < SCAN_BLK / 32) {
        int ws = warpsum[t];
#pragma unroll
        for (int o = SCAN_BLK / 64; o > 0; o >>= 1)
            ws += __shfl_down_sync(0xffffffffu, ws, o);
        if (t == 0) g_bsum[b] = ws;
    }
}

// ---------------------------------------------------------------------------
__global__ __launch_bounds__(SCAN_BLK) void k_scanC() {
    __shared__ int sh[SCAN_BLK];
    __shared__ int s_base;
    int t = threadIdx.x, b = blockIdx.x;

    if (t < 32) {
        int v = 0;
        for (int i = t; i < b; i += 32) v += g_bsum[i];
#pragma unroll
        for (int o = 16; o > 0; o >>= 1) v += __shfl_down_sync(0xffffffffu, v, o);
        if (t == 0) s_base = v;
    }

    int idx = b * SCAN_CHUNK + t * SCAN_ITEMS;
    int4 v = (idx < N_NODES + 4) ? ((const int4*)g_deg)[idx >> 2]
                                 : make_int4(0, 0, 0, 0);
    if (idx < N_NODES + 4)
        ((int4*)g_deg)[idx >> 2] = make_int4(0, 0, 0, 0);
    int d0 = (idx + 0 < N_NODES) ? v.x : 0;
    int d1 = (idx + 1 < N_NODES) ? v.y : 0;
    int d2 = (idx + 2 < N_NODES) ? v.z : 0;
    int d3 = (idx + 3 < N_NODES) ? v.w : 0;
    sh[t] = d0 + d1 + d2 + d3;
    __syncthreads();
#pragma unroll
    for (int d = 1; d < SCAN_BLK; d <<= 1) {
        int u = (t >= d) ? sh[t - d] : 0;
        __syncthreads();
        sh[t] += u;
        __syncthreads();
    }
    int run = s_base + ((t > 0) ? sh[t - 1] : 0);
    int dg[4] = {d0, d1, d2, d3};
#pragma unroll
    for (int j = 0; j < 4; j++) {
        int i = idx + j;
        if (i < N_NODES) {
            g_off[i] = run;
            g_cursor[i] = run;
            g_dinv[i] = rsqrtf((float)(dg[j] + 1));
            run += dg[j];
        }
    }
    if (b == SCAN_NBLK - 1 && t == SCAN_BLK - 1) g_off[N_NODES] = run;
}

// ---------------------------------------------------------------------------
// K3 (fused): blocks [0,FILL_BLOCKS) fill CSR; the rest run gemm1
// (z = dinv*(x@Wc), smem x staging, packed f32x2).
// ---------------------------------------------------------------------------
__global__ __launch_bounds__(256) void k_work(const float* __restrict__ x,
                                              const float* __restrict__ Wc,
                                              const void* __restrict__ ei) {
    extern __shared__ float sm[];

    if (blockIdx.x < FILL_BLOCKS) {
        __shared__ int s_flag;
        int use64 = detect_is64_block(ei, &s_flag);
        int tid = blockIdx.x * blockDim.x + threadIdx.x;
        int stride = FILL_BLOCKS * blockDim.x;
        for (int e = tid; e < N_EDGES; e += stride) {
            unsigned s = (unsigned)edge_at(ei, use64, e);
            unsigned d = (unsigned)edge_at(ei, use64, (size_t)N_EDGES + e);
            if (d < N_NODES && s < N_NODES) {
                int pos = atomicAdd(&g_cursor[d], 1);
                g_csr_src[pos] = (int)s;
            }
        }
        return;
    }

    float* Ws = sm;                          // 16384 floats
    float* xt = sm + D * D;                  // 8 warps * 8 rows * 128
    int tid = threadIdx.x, warp = tid >> 5, lane = tid & 31;
    int bid = blockIdx.x - FILL_BLOCKS;

    for (int i = tid; i < D * D / 4; i += 256)
        ((float4*)Ws)[i] = ((const float4*)Wc)[i];
    __syncthreads();

    float* xw = xt + warp * (RT * D);
    const int ngroups = (N_NODES + RT - 1) / RT;
    const int wstride = GEMM_BLOCKS * 8;
    for (int g = bid * 8 + warp; g < ngroups; g += wstride) {
        int row0 = g * RT;
#pragma unroll
        for (int r = 0; r < RT; r++) {
            int row = row0 + r;
            float4 v = (row < N_NODES) ? ((const float4*)(x + (size_t)row * D))[lane]
                                       : make_float4(0.f, 0.f, 0.f, 0.f);
            ((float4*)(xw + r * D))[lane] = v;
        }
        __syncwarp();

        unsigned long long a0[RT], a1[RT];
#pragma unroll
        for (int r = 0; r < RT; r++) { a0[r] = 0ull; a1[r] = 0ull; }
#pragma unroll 4
        for (int k = 0; k < D; k++) {
            ulonglong2 w = ((const ulonglong2*)(Ws + k * D))[lane];
#pragma unroll
            for (int r = 0; r < RT; r++) {
                unsigned xi = __float_as_uint(xw[r * D + k]);
                unsigned long long xp;
                PACK_DUP(xp, xi);
                FMA_X2(a0[r], xp, w.x);
                FMA_X2(a1[r], xp, w.y);
            }
        }
#pragma unroll
        for (int r = 0; r < RT; r++) {
            int row = row0 + r;
            if (row < N_NODES) {
                unsigned si = __float_as_uint(g_dinv[row]);
                unsigned long long sp, o0, o1;
                PACK_DUP(sp, si);
                MUL_X2(o0, a0[r], sp);
                MUL_X2(o1, a1[r], sp);
                ((ulonglong2*)(g_z + (size_t)row * D))[lane] = make_ulonglong2(o0, o1);
            }
        }
        __syncwarp();
    }
}

// ---------------------------------------------------------------------------
// K5: 512 threads (16 warps), RTF=8 rows per warp tile.
// Gather as R11 (FADD, 8-wide MLP, idx prefetch). Epilogue restructured for
// minimal smem-crossbar traffic: per j hoist 4xM1 + 4xM2 LDS.128 into regs
// (amortized over 8 rows), h read as uniform-address LDS.128 (broadcast,
// 1 crossbar cyc), x as broadcast LDG.
// ---------------------------------------------------------------------------
__global__ __launch_bounds__(512, 1) void k_final(const float* __restrict__ x,
                                                  const float* __restrict__ bc,
                                                  const float* __restrict__ W0,
                                                  const float* __restrict__ Wt,
                                                  float* __restrict__ out) {
    extern __shared__ float sm[];
    float* M1s = sm;                              // 16384
    float* M2s = sm + D * D;                      // 16384
    float* bcs = sm + 2 * D * D;                  // 128
    float* ht  = bcs + D;                         // 16 warps * 8 * 128 = 16384
    int*   ibase = (int*)(ht + FWARPS * RTF * D); // 16 warps * 64 ints
    int tid = threadIdx.x, warp = tid >> 5, lane = tid & 31;

    for (int i = tid; i < D * D / 4; i += 512) {
        float4 wt = ((const float4*)Wt)[i];
        float4 w0 = ((const float4*)W0)[i];
        int r = (i * 4) / D, c0 = (i * 4) % D;
        float m1v[4] = {wt.x, wt.y, wt.z, wt.w};
        int dd = r - c0;
        if (dd >= 0 && dd < 4) m1v[dd] += 1.0f;
        ((float4*)M1s)[i] = make_float4(m1v[0], m1v[1], m1v[2], m1v[3]);
        ((float4*)M2s)[i] = make_float4(w0.x - wt.x, w0.y - wt.y,
                                        w0.z - wt.z, w0.w - wt.w);
    }
    if (tid < D) bcs[tid] = bc[tid];
    __syncthreads();

    float* htw  = ht + warp * (RTF * D);
    int*   ibuf = ibase + warp * 64;              // two 32-entry halves

    const int ngroups = (N_NODES + RTF - 1) / RTF;
    const int wstride = gridDim.x * FWARPS;
    for (int g = blockIdx.x * FWARPS + warp; g < ngroups; g += wstride) {
        int row0 = g * RTF;

        int off_l = 0;
        if (lane <= RTF) {
            int rr = row0 + lane;
            off_l = __ldg(&g_off[rr < N_NODES ? rr : N_NODES]);
        }
        int rowE[RTF + 1];
#pragma unroll
        for (int r = 0; r <= RTF; r++)
            rowE[r] = __shfl_sync(0xffffffffu, off_l, r);

        {
            int n0 = rowE[1] - rowE[0];
            if (lane < (n0 < 32 ? n0 : 32)) ibuf[lane] = __ldg(&g_csr_src[rowE[0] + lane]);
        }

        // ---- gather phase with one-row-ahead idx prefetch
#pragma unroll
        for (int r = 0; r < RTF; r++) {
            __syncwarp();
            int* cur = ibuf + ((r & 1) << 5);
            if (r + 1 < RTF) {
                int* nxt = ibuf + (((r + 1) & 1) << 5);
                int nn = rowE[r + 2] - rowE[r + 1];
                if (lane < (nn < 32 ? nn : 32))
                    nxt[lane] = __ldg(&g_csr_src[rowE[r + 1] + lane]);
            }

            int row = row0 + r;
            if (row >= N_NODES) {
                ((float4*)(htw + r * D))[lane] = make_float4(0.f, 0.f, 0.f, 0.f);
                continue;
            }
            size_t base = (size_t)row * D;
            float4 acc = ((const float4*)(g_z + base))[lane];
            int n = rowE[r + 1] - rowE[r];
            int m = n < 32 ? n : 32;
            int i = 0;
            for (; i + 7 < m; i += 8) {
                int s0 = cur[i];     int s1 = cur[i + 1];
                int s2 = cur[i + 2]; int s3 = cur[i + 3];
                int s4 = cur[i + 4]; int s5 = cur[i + 5];
                int s6 = cur[i + 6]; int s7 = cur[i + 7];
                float4 v0 = ((const float4*)(g_z + (size_t)s0 * D))[lane];
                float4 v1 = ((const float4*)(g_z + (size_t)s1 * D))[lane];
                float4 v2 = ((const float4*)(g_z + (size_t)s2 * D))[lane];
                float4 v3 = ((const float4*)(g_z + (size_t)s3 * D))[lane];
                float4 v4 = ((const float4*)(g_z + (size_t)s4 * D))[lane];
                float4 v5 = ((const float4*)(g_z + (size_t)s5 * D))[lane];
                float4 v6 = ((const float4*)(g_z + (size_t)s6 * D))[lane];
                float4 v7 = ((const float4*)(g_z + (size_t)s7 * D))[lane];
                acc.x += ((v0.x + v1.x) + (v2.x + v3.x)) + ((v4.x + v5.x) + (v6.x + v7.x));
                acc.y += ((v0.y + v1.y) + (v2.y + v3.y)) + ((v4.y + v5.y) + (v6.y + v7.y));
                acc.z += ((v0.z + v1.z) + (v2.z + v3.z)) + ((v4.z + v5.z) + (v6.z + v7.z));
                acc.w += ((v0.w + v1.w) + (v2.w + v3.w)) + ((v4.w + v5.w) + (v6.w + v7.w));
            }
            for (; i < m; i++) {
                int s0 = cur[i];
                float4 v0 = ((const float4*)(g_z + (size_t)s0 * D))[lane];
                acc.x += v0.x; acc.y += v0.y; acc.z += v0.z; acc.w += v0.w;
            }
            for (int e = rowE[r] + 32; e < rowE[r + 1]; e++) {
                int s0 = __ldg(&g_csr_src[e]);
                float4 v0 = ((const float4*)(g_z + (size_t)s0 * D))[lane];
                acc.x += v0.x; acc.y += v0.y; acc.z += v0.z; acc.w += v0.w;
            }

            float s = __ldg(&g_dinv[row]);
            float4 b4 = ((const float4*)bcs)[lane];
            float4 h4;
            h4.x = s * acc.x + b4.x;
            h4.y = s * acc.y + b4.y;
            h4.z = s * acc.z + b4.z;
            h4.w = s * acc.w + b4.w;
            ((float4*)(htw + r * D))[lane] = h4;
        }
        __syncwarp();

        // ---- dual GEMM: o[r] = h[r] @ M1 + x[r] @ M2
        // Weights hoisted per j (8 LDS.128 amortized over 8 rows); h uniform
        // LDS.128 broadcast; x broadcast LDG.
        unsigned long long o0[RTF], o1[RTF];
#pragma unroll
        for (int r = 0; r < RTF; r++) { o0[r] = 0ull; o1[r] = 0ull; }

        for (int j = 0; j < D / 4; j++) {
            ulonglong2 M1v[4], M2v[4];
#pragma unroll
            for (int kk = 0; kk < 4; kk++) {
                M1v[kk] = ((const ulonglong2*)(M1s + (4 * j + kk) * D))[lane];
                M2v[kk] = ((const ulonglong2*)(M2s + (4 * j + kk) * D))[lane];
            }
#pragma unroll
            for (int r = 0; r < RTF; r++) {
                int row = row0 + r;
                // uniform-address LDS.128 (broadcast): 4 h values for k=4j..4j+3
                float4 hv = *(const float4*)(htw + r * D + 4 * j);
                float4 xv = (row < N_NODES)
                          ? __ldg(&((const float4*)(x + (size_t)row * D))[j])
                          : make_float4(0.f, 0.f, 0.f, 0.f);
#pragma unroll
                for (int kk = 0; kk < 4; kk++) {
                    unsigned long long hp, xp;
                    PACK_DUP(hp, __float_as_uint(f4c(hv, kk)));
                    PACK_DUP(xp, __float_as_uint(f4c(xv, kk)));
                    FMA_X2(o0[r], hp, M1v[kk].x);
                    FMA_X2(o1[r], hp, M1v[kk].y);
                    FMA_X2(o0[r], xp, M2v[kk].x);
                    FMA_X2(o1[r], xp, M2v[kk].y);
                }
            }
        }
#pragma unroll
        for (int r = 0; r < RTF; r++) {
            int row = row0 + r;
            if (row < N_NODES)
                ((ulonglong2*)(out + (size_t)row * D))[lane] = make_ulonglong2(o0[r], o1[r]);
        }
        __syncwarp();
    }
}

// ---------------------------------------------------------------------------
extern "C" void kernel_launch(void* const* d_in, const int* in_sizes, int n_in,
                              void* d_out, int out_size) {
    const float* x  = (const float*)d_in[0];
    const void*  ei = d_in[1];
    const float* Wc = (const float*)d_in[2];
    const float* bc = (const float*)d_in[3];
    const float* W0 = (const float*)d_in[4];
    const float* Wt = (const float*)d_in[5];

    {
        const float* fx = nullptr; const void* fei = nullptr;
        const float* fbc = nullptr;
        const float* w[3] = {nullptr, nullptr, nullptr}; int nw = 0;
        for (int i = 0; i < n_in; i++) {
            int sz = in_sizes[i];
            if (sz == N_NODES * D)                           fx  = (const float*)d_in[i];
            else if (sz == 2 * N_EDGES || sz == 4 * N_EDGES) fei = d_in[i];
            else if (sz == D)                                fbc = (const float*)d_in[i];
            else if (sz == D * D && nw < 3)                  w[nw++] = (const float*)d_in[i];
        }
        if (fx)  x  = fx;
        if (fei) ei = fei;
        if (fbc) bc = fbc;
        if (nw == 3) { Wc = w[0]; W0 = w[1]; Wt = w[2]; }
    }
    float* out = (float*)d_out;

    int smem_work  = (D * D + 8 * RT * D) * (int)sizeof(float);               // 98,304 B
    int smem_final = (2 * D * D + D + FWARPS * RTF * D) * (int)sizeof(float)
                     + FWARPS * 64 * (int)sizeof(int);                         // 201,216 B
    cudaFuncSetAttribute(k_work, cudaFuncAttributeMaxDynamicSharedMemorySize, smem_work);
    cudaFuncSetAttribute(k_final, cudaFuncAttributeMaxDynamicSharedMemorySize, smem_final);

    k_degree<<<512, 256>>>(ei);
    k_scanA<<<SCAN_NBLK, SCAN_BLK>>>();
    k_scanC<<<SCAN_NBLK, SCAN_BLK>>>();
    k_work<<<FILL_BLOCKS + GEMM_BLOCKS, 256, smem_work>>>(x, Wc, ei);
    k_final<<<148, 512, smem_final>>>(x, bc, W0, Wt, out);
}

// round 17
// speedup vs baseline: 1.1854x; 1.0081x over previous
#include <cuda_runtime.h>
#include <cstdint>

#define N_NODES 50000
#define N_EDGES 800000
#define D       128
#define RT      8                      // rows per warp tile (gemm)
#define RTF     8                      // rows per warp tile (final)
#define FWARPS  16                     // warps per block in k_final

#define SCAN_ITEMS 4
#define SCAN_BLK   256
#define SCAN_CHUNK (SCAN_BLK * SCAN_ITEMS)                       // 1024
#define SCAN_NBLK  ((N_NODES + SCAN_CHUNK - 1) / SCAN_CHUNK)     // 49

#define FILL_BLOCKS 96
#define GEMM_BLOCKS 296

// per-k stride (in floats) of the packed row-pair x tile: 4 pairs * 2 floats
// + 2 pad = 10 floats = 40 B  (40B stride -> <=2-way bank conflict on staging,
// 8B-aligned broadcasts in the k loop)
#define XPAIR_STRIDE 10

// ---- packed f32x2 helpers ----
#define FMA_X2(acc, a, b) \
    asm("fma.rn.f32x2 %0, %1, %2, %0;" : "+l"(acc) : "l"(a), "l"(b))
#define MUL_X2(out, a, b) \
    asm("mul.rn.f32x2 %0, %1, %2;" : "=l"(out) : "l"(a), "l"(b))
#define PACK_DUP(out, xi) \
    asm("mov.b64 %0, {%1, %1};" : "=l"(out) : "r"(xi))
#define PACK_PAIR(out, a, b) \
    asm("mov.b64 %0, {%1, %2};" : "=l"(out) : "r"(a), "r"(b))
#define UNPACK_PAIR(lo, hi, in) \
    asm("mov.b64 {%0, %1}, %2;" : "=r"(lo), "=r"(hi) : "l"(in))

__device__ __forceinline__ float f4c(const float4& v, int kk) {
    return kk == 0 ? v.x : kk == 1 ? v.y : kk == 2 ? v.z : v.w;
}

// ---- scratch (device globals; no allocation allowed) ----
__device__ __align__(16) float g_z[(size_t)N_NODES * D];    // z = dinv * (x @ Wc)
__device__ __align__(16) float g_dinv[N_NODES];
__device__ __align__(16) int   g_deg[N_NODES + 4];          // zero-init; re-zeroed by k_scan
__device__ int   g_off[N_NODES + 1];
__device__ int   g_cursor[N_NODES];
__device__ int   g_csr_src[N_EDGES];
__device__ int   g_bsum[SCAN_NBLK];
__device__ int   g_scan_arrive;        // reset by k_work fill path

// ---------------------------------------------------------------------------
__device__ __forceinline__ int detect_is64_block(const void* ei, int* s_flag) {
    if (threadIdx.x == 0) {
        const long long* p = (const long long*)ei;
        int use64 = 1;
        for (int i = 0; i < 64; i++)
            if ((unsigned long long)p[i] >> 32) { use64 = 0; break; }
        *s_flag = use64;
    }
    __syncthreads();
    return *s_flag;
}

__device__ __forceinline__ int edge_at(const void* ei, int use64, size_t idx) {
    return use64 ? (int)((const long long*)ei)[idx]
                 : ((const int*)ei)[idx];
}

// ---------------------------------------------------------------------------
__global__ void k_degree(const void* __restrict__ ei) {
    __shared__ int s_flag;
    int use64 = detect_is64_block(ei, &s_flag);
    int tid = blockIdx.x * blockDim.x + threadIdx.x;
    int stride = gridDim.x * blockDim.x;
    for (int e = tid; e < N_EDGES; e += stride) {
        unsigned d = (unsigned)edge_at(ei, use64, (size_t)N_EDGES + e);
        if (d < N_NODES) atomicAdd(&g_deg[d], 1);
    }
}

// ---------------------------------------------------------------------------
// Merged scan (single launch, 49 blocks — all trivially co-resident, so the
// same-kernel arrival spin is safe; empirically validated in R13).
// ---------------------------------------------------------------------------
__global__ __launch_bounds__(SCAN_BLK) void k_scan() {
    __shared__ int sh[SCAN_BLK];
    __shared__ int warpsum[SCAN_BLK / 32];
    __shared__ int s_base;
    int t = threadIdx.x, b = blockIdx.x;

    int idx = b * SCAN_CHUNK + t * SCAN_ITEMS;
    int4 v = (idx < N_NODES + 4) ? ((const int4*)g_deg)[idx >> 2]
                                 : make_int4(0, 0, 0, 0);
    if (idx < N_NODES + 4)
        ((int4*)g_deg)[idx >> 2] = make_int4(0, 0, 0, 0);   // reset for replay
    int d0 = (idx + 0 < N_NODES) ? v.x : 0;
    int d1 = (idx + 1 < N_NODES) ? v.y : 0;
    int d2 = (idx + 2 < N_NODES) ? v.z : 0;
    int d3 = (idx + 3 < N_NODES) ? v.w : 0;
    int s = d0 + d1 + d2 + d3;
    sh[t] = s;

    int ws = s;
#pragma unroll
    for (int o = 16; o > 0; o >>= 1) ws += __shfl_down_sync(0xffffffffu, ws, o);
    if ((t & 31) == 0) warpsum[t >> 5] = ws;
    __syncthreads();

    if (t == 0) {
        int tot = 0;
#pragma unroll
        for (int i = 0; i < SCAN_BLK / 32; i++) tot += warpsum[i];
        g_bsum[b] = tot;
        __threadfence();
        atomicAdd(&g_scan_arrive, 1);
        while (atomicAdd(&g_scan_arrive, 0) < SCAN_NBLK) __nanosleep(64);
    }
    __syncthreads();

    if (t < 32) {
        int vs = 0;
        for (int i = t; i < b; i += 32) vs += atomicAdd(&g_bsum[i], 0);
#pragma unroll
        for (int o = 16; o > 0; o >>= 1) vs += __shfl_down_sync(0xffffffffu, vs, o);
        if (t == 0) s_base = vs;
    }
    __syncthreads();

#pragma unroll
    for (int d = 1; d < SCAN_BLK; d <<= 1) {
        int u = (t >= d) ? sh[t - d] : 0;
        __syncthreads();
        sh[t] += u;
        __syncthreads();
    }
    int run = s_base + ((t > 0) ? sh[t - 1] : 0);
    int dg[4] = {d0, d1, d2, d3};
#pragma unroll
    for (int j = 0; j < 4; j++) {
        int i = idx + j;
        if (i < N_NODES) {
            g_off[i] = run;
            g_cursor[i] = run;
            g_dinv[i] = rsqrtf((float)(dg[j] + 1));
            run += dg[j];
        }
    }
    if (b == SCAN_NBLK - 1 && t == SCAN_BLK - 1) g_off[N_NODES] = run;
}

// ---------------------------------------------------------------------------
// K3 (fused): blocks [0,FILL_BLOCKS) fill CSR (+ reset scan counter); the
// rest run gemm1 with ROW-PAIR f32x2 packing:
//   x staged as {x[2p][k], x[2p+1][k]} pairs, stride 40B per k.
//   Per k: 1 LDS.128 (w) + 4 PACK_DUP(w) + 4 broadcast LDS.64 (pairs)
//          + 16 FFMA2  (25 issues vs 33 in the col-pair version).
// N_NODES % 8 == 0 -> no row guards needed in the gemm path.
// ---------------------------------------------------------------------------
__global__ __launch_bounds__(256) void k_work(const float* __restrict__ x,
                                              const float* __restrict__ Wc,
                                              const void* __restrict__ ei) {
    extern __shared__ float sm[];

    if (blockIdx.x < FILL_BLOCKS) {
        if (blockIdx.x == 0 && threadIdx.x == 0) g_scan_arrive = 0;  // replay reset
        __shared__ int s_flag;
        int use64 = detect_is64_block(ei, &s_flag);
        int tid = blockIdx.x * blockDim.x + threadIdx.x;
        int stride = FILL_BLOCKS * blockDim.x;
        for (int e = tid; e < N_EDGES; e += stride) {
            unsigned s = (unsigned)edge_at(ei, use64, e);
            unsigned d = (unsigned)edge_at(ei, use64, (size_t)N_EDGES + e);
            if (d < N_NODES && s < N_NODES) {
                int pos = atomicAdd(&g_cursor[d], 1);
                g_csr_src[pos] = (int)s;
            }
        }
        return;
    }

    float* Ws = sm;                          // 16384 floats (64 KB)
    float* xt = sm + D * D;                  // 8 warps * 128 * XPAIR_STRIDE floats
    int tid = threadIdx.x, warp = tid >> 5, lane = tid & 31;
    int bid = blockIdx.x - FILL_BLOCKS;

    for (int i = tid; i < D * D / 4; i += 256)
        ((float4*)Ws)[i] = ((const float4*)Wc)[i];
    __syncthreads();

    float* xw = xt + warp * (D * XPAIR_STRIDE);
    const int ngroups = N_NODES / RT;        // 6250, exact
    const int wstride = GEMM_BLOCKS * 8;
    for (int g = bid * 8 + warp; g < ngroups; g += wstride) {
        int row0 = g * RT;

        // stage x as row pairs: xw[k*XPAIR_STRIDE + 2p .. +2p+1] = {xA[k], xB[k]}
#pragma unroll
        for (int p = 0; p < 4; p++) {
            int rowA = row0 + 2 * p;
            float4 a = ((const float4*)(x + (size_t)rowA * D))[lane];
            float4 b = ((const float4*)(x + (size_t)(rowA + 1) * D))[lane];
#pragma unroll
            for (int kk = 0; kk < 4; kk++) {
                int k = 4 * lane + kk;
                float2* dst = (float2*)(xw + k * XPAIR_STRIDE + 2 * p);
                *dst = make_float2(f4c(a, kk), f4c(b, kk));
            }
        }
        __syncwarp();

        unsigned long long acc[4][4];
#pragma unroll
        for (int p = 0; p < 4; p++)
#pragma unroll
            for (int c = 0; c < 4; c++) acc[p][c] = 0ull;

#pragma unroll 4
        for (int k = 0; k < D; k++) {
            float4 wv = ((const float4*)(Ws + k * D))[lane];
            unsigned long long wd0, wd1, wd2, wd3;
            PACK_DUP(wd0, __float_as_uint(wv.x));
            PACK_DUP(wd1, __float_as_uint(wv.y));
            PACK_DUP(wd2, __float_as_uint(wv.z));
            PACK_DUP(wd3, __float_as_uint(wv.w));
            const float* xk = xw + k * XPAIR_STRIDE;
#pragma unroll
            for (int p = 0; p < 4; p++) {
                unsigned long long xp = *(const unsigned long long*)(xk + 2 * p);
                FMA_X2(acc[p][0], xp, wd0);
                FMA_X2(acc[p][1], xp, wd1);
                FMA_X2(acc[p][2], xp, wd2);
                FMA_X2(acc[p][3], xp, wd3);
            }
        }

        // scale by dinv (packed per row pair) and store both rows
#pragma unroll
        for (int p = 0; p < 4; p++) {
            int rowA = row0 + 2 * p;
            unsigned long long sp;
            PACK_PAIR(sp, __float_as_uint(g_dinv[rowA]),
                          __float_as_uint(g_dinv[rowA + 1]));
            unsigned long long t0, t1, t2, t3;
            MUL_X2(t0, acc[p][0], sp);
            MUL_X2(t1, acc[p][1], sp);
            MUL_X2(t2, acc[p][2], sp);
            MUL_X2(t3, acc[p][3], sp);
            unsigned a0, b0, a1, b1, a2, b2, a3, b3;
            UNPACK_PAIR(a0, b0, t0);
            UNPACK_PAIR(a1, b1, t1);
            UNPACK_PAIR(a2, b2, t2);
            UNPACK_PAIR(a3, b3, t3);
            float4 oA = make_float4(__uint_as_float(a0), __uint_as_float(a1),
                                    __uint_as_float(a2), __uint_as_float(a3));
            float4 oB = make_float4(__uint_as_float(b0), __uint_as_float(b1),
                                    __uint_as_float(b2), __uint_as_float(b3));
            ((float4*)(g_z + (size_t)rowA * D))[lane] = oA;
            ((float4*)(g_z + (size_t)(rowA + 1) * D))[lane] = oB;
        }
        __syncwarp();
    }
}

// ---------------------------------------------------------------------------
// K-FINAL: unchanged from R14 (512 thr, RTF=8, crossbar-lean epilogue).
// ---------------------------------------------------------------------------
__global__ __launch_bounds__(512, 1) void k_final(const float* __restrict__ x,
                                                  const float* __restrict__ bc,
                                                  const float* __restrict__ W0,
                                                  const float* __restrict__ Wt,
                                                  float* __restrict__ out) {
    extern __shared__ float sm[];
    float* M1s = sm;                              // 16384
    float* M2s = sm + D * D;                      // 16384
    float* bcs = sm + 2 * D * D;                  // 128
    float* ht  = bcs + D;                         // 16 warps * 8 * 128 = 16384
    int*   ibase = (int*)(ht + FWARPS * RTF * D); // 16 warps * 64 ints
    int tid = threadIdx.x, warp = tid >> 5, lane = tid & 31;

    for (int i = tid; i < D * D / 4; i += 512) {
        float4 wt = ((const float4*)Wt)[i];
        float4 w0 = ((const float4*)W0)[i];
        int r = (i * 4) / D, c0 = (i * 4) % D;
        float m1v[4] = {wt.x, wt.y, wt.z, wt.w};
        int dd = r - c0;
        if (dd >= 0 && dd < 4) m1v[dd] += 1.0f;
        ((float4*)M1s)[i] = make_float4(m1v[0], m1v[1], m1v[2], m1v[3]);
        ((float4*)M2s)[i] = make_float4(w0.x - wt.x, w0.y - wt.y,
                                        w0.z - wt.z, w0.w - wt.w);
    }
    if (tid < D) bcs[tid] = bc[tid];
    __syncthreads();

    float* htw  = ht + warp * (RTF * D);
    int*   ibuf = ibase + warp * 64;              // two 32-entry halves

    const int ngroups = (N_NODES + RTF - 1) / RTF;
    const int wstride = gridDim.x * FWARPS;
    for (int g = blockIdx.x * FWARPS + warp; g < ngroups; g += wstride) {
        int row0 = g * RTF;

        int off_l = 0;
        if (lane <= RTF) {
            int rr = row0 + lane;
            off_l = __ldg(&g_off[rr < N_NODES ? rr : N_NODES]);
        }
        int rowE[RTF + 1];
#pragma unroll
        for (int r = 0; r <= RTF; r++)
            rowE[r] = __shfl_sync(0xffffffffu, off_l, r);

        {
            int n0 = rowE[1] - rowE[0];
            if (lane < (n0 < 32 ? n0 : 32)) ibuf[lane] = __ldg(&g_csr_src[rowE[0] + lane]);
        }

        // ---- gather phase with one-row-ahead idx prefetch
#pragma unroll
        for (int r = 0; r < RTF; r++) {
            __syncwarp();
            int* cur = ibuf + ((r & 1) << 5);
            if (r + 1 < RTF) {
                int* nxt = ibuf + (((r + 1) & 1) << 5);
                int nn = rowE[r + 2] - rowE[r + 1];
                if (lane < (nn < 32 ? nn : 32))
                    nxt[lane] = __ldg(&g_csr_src[rowE[r + 1] + lane]);
            }

            int row = row0 + r;
            if (row >= N_NODES) {
                ((float4*)(htw + r * D))[lane] = make_float4(0.f, 0.f, 0.f, 0.f);
                continue;
            }
            size_t base = (size_t)row * D;
            float4 acc = ((const float4*)(g_z + base))[lane];
            int n = rowE[r + 1] - rowE[r];
            int m = n < 32 ? n : 32;
            int i = 0;
            for (; i + 7 < m; i += 8) {
                int s0 = cur[i];     int s1 = cur[i + 1];
                int s2 = cur[i + 2]; int s3 = cur[i + 3];
                int s4 = cur[i + 4]; int s5 = cur[i + 5];
                int s6 = cur[i + 6]; int s7 = cur[i + 7];
                float4 v0 = ((const float4*)(g_z + (size_t)s0 * D))[lane];
                float4 v1 = ((const float4*)(g_z + (size_t)s1 * D))[lane];
                float4 v2 = ((const float4*)(g_z + (size_t)s2 * D))[lane];
                float4 v3 = ((const float4*)(g_z + (size_t)s3 * D))[lane];
                float4 v4 = ((const float4*)(g_z + (size_t)s4 * D))[lane];
                float4 v5 = ((const float4*)(g_z + (size_t)s5 * D))[lane];
                float4 v6 = ((const float4*)(g_z + (size_t)s6 * D))[lane];
                float4 v7 = ((const float4*)(g_z + (size_t)s7 * D))[lane];
                acc.x += ((v0.x + v1.x) + (v2.x + v3.x)) + ((v4.x + v5.x) + (v6.x + v7.x));
                acc.y += ((v0.y + v1.y) + (v2.y + v3.y)) + ((v4.y + v5.y) + (v6.y + v7.y));
                acc.z += ((v0.z + v1.z) + (v2.z + v3.z)) + ((v4.z + v5.z) + (v6.z + v7.z));
                acc.w += ((v0.w + v1.w) + (v2.w + v3.w)) + ((v4.w + v5.w) + (v6.w + v7.w));
            }
            for (; i < m; i++) {
                int s0 = cur[i];
                float4 v0 = ((const float4*)(g_z + (size_t)s0 * D))[lane];
                acc.x += v0.x; acc.y += v0.y; acc.z += v0.z; acc.w += v0.w;
            }
            for (int e = rowE[r] + 32; e < rowE[r + 1]; e++) {
                int s0 = __ldg(&g_csr_src[e]);
                float4 v0 = ((const float4*)(g_z + (size_t)s0 * D))[lane];
                acc.x += v0.x; acc.y += v0.y; acc.z += v0.z; acc.w += v0.w;
            }

            float s = __ldg(&g_dinv[row]);
            float4 b4 = ((const float4*)bcs)[lane];
            float4 h4;
            h4.x = s * acc.x + b4.x;
            h4.y = s * acc.y + b4.y;
            h4.z = s * acc.z + b4.z;
            h4.w = s * acc.w + b4.w;
            ((float4*)(htw + r * D))[lane] = h4;
        }
        __syncwarp();

        // ---- dual GEMM: o[r] = h[r] @ M1 + x[r] @ M2
        unsigned long long o0[RTF], o1[RTF];
#pragma unroll
        for (int r = 0; r < RTF; r++) { o0[r] = 0ull; o1[r] = 0ull; }

        for (int j = 0; j < D / 4; j++) {
            ulonglong2 M1v[4], M2v[4];
#pragma unroll
            for (int kk = 0; kk < 4; kk++) {
                M1v[kk] = ((const ulonglong2*)(M1s + (4 * j + kk) * D))[lane];
                M2v[kk] = ((const ulonglong2*)(M2s + (4 * j + kk) * D))[lane];
            }
#pragma unroll
            for (int r = 0; r < RTF; r++) {
                int row = row0 + r;
                float4 hv = *(const float4*)(htw + r * D + 4 * j);
                float4 xv = (row < N_NODES)
                          ? __ldg(&((const float4*)(x + (size_t)row * D))[j])
                          : make_float4(0.f, 0.f, 0.f, 0.f);
#pragma unroll
                for (int kk = 0; kk < 4; kk++) {
                    unsigned long long hp, xp;
                    PACK_DUP(hp, __float_as_uint(f4c(hv, kk)));
                    PACK_DUP(xp, __float_as_uint(f4c(xv, kk)));
                    FMA_X2(o0[r], hp, M1v[kk].x);
                    FMA_X2(o1[r], hp, M1v[kk].y);
                    FMA_X2(o0[r], xp, M2v[kk].x);
                    FMA_X2(o1[r], xp, M2v[kk].y);
                }
            }
        }
#pragma unroll
        for (int r = 0; r < RTF; r++) {
            int row = row0 + r;
            if (row < N_NODES)
                ((ulonglong2*)(out + (size_t)row * D))[lane] = make_ulonglong2(o0[r], o1[r]);
        }
        __syncwarp();
    }
}

// ---------------------------------------------------------------------------
extern "C" void kernel_launch(void* const* d_in, const int* in_sizes, int n_in,
                              void* d_out, int out_size) {
    const float* x  = (const float*)d_in[0];
    const void*  ei = d_in[1];
    const float* Wc = (const float*)d_in[2];
    const float* bc = (const float*)d_in[3];
    const float* W0 = (const float*)d_in[4];
    const float* Wt = (const float*)d_in[5];

    {
        const float* fx = nullptr; const void* fei = nullptr;
        const float* fbc = nullptr;
        const float* w[3] = {nullptr, nullptr, nullptr}; int nw = 0;
        for (int i = 0; i < n_in; i++) {
            int sz = in_sizes[i];
            if (sz == N_NODES * D)                           fx  = (const float*)d_in[i];
            else if (sz == 2 * N_EDGES || sz == 4 * N_EDGES) fei = d_in[i];
            else if (sz == D)                                fbc = (const float*)d_in[i];
            else if (sz == D * D && nw < 3)                  w[nw++] = (const float*)d_in[i];
        }
        if (fx)  x  = fx;
        if (fei) ei = fei;
        if (fbc) bc = fbc;
        if (nw == 3) { Wc = w[0]; W0 = w[1]; Wt = w[2]; }
    }
    float* out = (float*)d_out;

    int smem_work  = (D * D + 8 * D * XPAIR_STRIDE) * (int)sizeof(float);     // 106,496 B
    int smem_final = (2 * D * D + D + FWARPS * RTF * D) * (int)sizeof(float)
                     + FWARPS * 64 * (int)sizeof(int);                         // 201,216 B
    cudaFuncSetAttribute(k_work, cudaFuncAttributeMaxDynamicSharedMemorySize, smem_work);
    cudaFuncSetAttribute(k_final, cudaFuncAttributeMaxDynamicSharedMemorySize, smem_final);

    k_degree<<<512, 256>>>(ei);
    k_scan<<<SCAN_NBLK, SCAN_BLK>>>();
    k_work<<<FILL_BLOCKS + GEMM_BLOCKS, 256, smem_work>>>(x, Wc, ei);
    k_final<<<148, 512, smem_final>>>(x, bc, W0, Wt, out);
}